// round 5
// baseline (speedup 1.0000x reference)
#include <cuda_runtime.h>
#include <stdint.h>

// Fixed shapes from reference setup_inputs
#define B_  16
#define C_  3
#define H_  1024
#define W_  1024
#define CP  35                 // 1024/32 + 3
#define CP_HALF 17.0f          // (CP-1)/2
#define CP_ELEMS (2*CP*CP)     // 2450 floats
#define PLANE (H_*W_)          // 1<<20

// ---------------------------------------------------------------------------
// Kernel A: deformation field (2, H, W), batch-invariant, written once.
// 4 pixels per thread, float4 stores. One block row = one image row.
// ---------------------------------------------------------------------------
__global__ __launch_bounds__(256)
void df_kernel(const float* __restrict__ cp, float* __restrict__ df_out)
{
    __shared__ float s_cp[CP_ELEMS];
    const int tid = threadIdx.x;
    #pragma unroll
    for (int t = tid; t < CP_ELEMS; t += 256)
        s_cp[t] = cp[t];
    __syncthreads();

    const int i  = blockIdx.y;
    const int j0 = tid * 4;

    const float gy = -1.0f + 2.0f * (float)i * (1.0f / (float)(H_ - 1));
    // y-part of cp interpolation is row-constant
    const float cpy = gy * CP_HALF + CP_HALF;
    float ciy = (cpy + 1.0f) * 0.5f * (float)(CP - 1);
    ciy = fminf(fmaxf(ciy, 0.0f), (float)(CP - 1));
    const float ciy0f = floorf(ciy);
    const float cwy = ciy - ciy0f;
    const int ciy0 = (int)ciy0f;
    const int ciy1 = min(ciy0 + 1, CP - 1);

    float4 d0, d1;
    float* d0p = &d0.x;
    float* d1p = &d1.x;

    #pragma unroll
    for (int k = 0; k < 4; k++) {
        const int j = j0 + k;
        const float gx = -1.0f + 2.0f * (float)j * (1.0f / (float)(W_ - 1));
        const float cpx = gx * CP_HALF + CP_HALF;
        float cix = (cpx + 1.0f) * 0.5f * (float)(CP - 1);
        cix = fminf(fmaxf(cix, 0.0f), (float)(CP - 1));
        const float cix0f = floorf(cix);
        const float cwx = cix - cix0f;
        const int cix0 = (int)cix0f;
        const int cix1 = min(cix0 + 1, CP - 1);

        const int o00 = ciy0 * CP + cix0;
        const int o01 = ciy0 * CP + cix1;
        const int o10 = ciy1 * CP + cix0;
        const int o11 = ciy1 * CP + cix1;

        {
            const float v00 = s_cp[o00], v01 = s_cp[o01];
            const float v10 = s_cp[o10], v11 = s_cp[o11];
            const float top = v00 * (1.0f - cwx) + v01 * cwx;
            const float bot = v10 * (1.0f - cwx) + v11 * cwx;
            d0p[k] = top * (1.0f - cwy) + bot * cwy;
        }
        {
            const float v00 = s_cp[CP*CP + o00], v01 = s_cp[CP*CP + o01];
            const float v10 = s_cp[CP*CP + o10], v11 = s_cp[CP*CP + o11];
            const float top = v00 * (1.0f - cwx) + v01 * cwx;
            const float bot = v10 * (1.0f - cwx) + v11 * cwx;
            d1p[k] = top * (1.0f - cwy) + bot * cwy;
        }
    }

    const int p = i * W_ + j0;
    *(float4*)(df_out + p)         = d0;
    *(float4*)(df_out + PLANE + p) = d1;
}

// ---------------------------------------------------------------------------
// Kernel B: per-batch bilinear gather, 4 pixels/thread.
// df read via float4 (L2-resident), output via float4 stores.
// Per channel: 16 independent gather LDGs in flight -> high MLP.
// ---------------------------------------------------------------------------
__global__ __launch_bounds__(256)
void warp_kernel(const float* __restrict__ x,
                 const float* __restrict__ df,
                 float* __restrict__ out)
{
    const int i  = blockIdx.y;
    const int b  = blockIdx.z;
    const int j0 = threadIdx.x * 4;
    const int p  = i * W_ + j0;

    const float4 d0 = __ldg((const float4*)(df + p));          // df channel 0 (y-shift)
    const float4 d1 = __ldg((const float4*)(df + PLANE + p));  // df channel 1 (x-shift)
    const float* d0p = &d0.x;
    const float* d1p = &d1.x;

    const float gy = -1.0f + 2.0f * (float)i * (1.0f / (float)(H_ - 1));

    int   base[4], dx[4], dyw[4];
    float w00[4], w01[4], w10[4], w11[4];

    #pragma unroll
    for (int k = 0; k < 4; k++) {
        const int j = j0 + k;
        const float gx = -1.0f + 2.0f * (float)j * (1.0f / (float)(W_ - 1));

        float ix = (gx + d1p[k] + 1.0f) * 0.5f * (float)(W_ - 1);
        float iy = (gy + d0p[k] + 1.0f) * 0.5f * (float)(H_ - 1);
        ix = fminf(fmaxf(ix, 0.0f), (float)(W_ - 1));
        iy = fminf(fmaxf(iy, 0.0f), (float)(H_ - 1));
        const float ix0f = floorf(ix);
        const float iy0f = floorf(iy);
        const float wx = ix - ix0f;
        const float wy = iy - iy0f;
        const int ix0 = (int)ix0f;
        const int iy0 = (int)iy0f;
        dx[k]  = (ix0 < W_ - 1) ? 1 : 0;
        dyw[k] = (iy0 < H_ - 1) ? W_ : 0;
        base[k] = iy0 * W_ + ix0;

        w00[k] = (1.0f - wx) * (1.0f - wy);
        w01[k] = wx * (1.0f - wy);
        w10[k] = (1.0f - wx) * wy;
        w11[k] = wx * wy;
    }

    const float* xb = x + (size_t)(b * C_) * PLANE;
    float* ob = out + (size_t)(b * C_) * PLANE + p;

    #pragma unroll
    for (int c = 0; c < C_; c++) {
        const float* xp = xb + (size_t)c * PLANE;
        float v00[4], v01[4], v10[4], v11[4];
        // issue all 16 gathers back-to-back for max MLP
        #pragma unroll
        for (int k = 0; k < 4; k++) {
            v00[k] = __ldg(xp + base[k]);
            v01[k] = __ldg(xp + base[k] + dx[k]);
            v10[k] = __ldg(xp + base[k] + dyw[k]);
            v11[k] = __ldg(xp + base[k] + dyw[k] + dx[k]);
        }
        float4 r;
        float* rp = &r.x;
        #pragma unroll
        for (int k = 0; k < 4; k++)
            rp[k] = v00[k]*w00[k] + v01[k]*w01[k] + v10[k]*w10[k] + v11[k]*w11[k];
        *(float4*)(ob + (size_t)c * PLANE) = r;
    }
}

extern "C" void kernel_launch(void* const* d_in, const int* in_sizes, int n_in,
                              void* d_out, int out_size)
{
    const float* x  = (const float*)d_in[0];    // (16,3,1024,1024)
    const float* cp = (const float*)d_in[1];    // (1,2,35,35)
    float* out = (float*)d_out;                 // transformed (48M) ++ df (2M)
    float* df  = out + (size_t)B_ * C_ * PLANE;

    dim3 block(256, 1, 1);
    df_kernel<<<dim3(1, H_, 1), block>>>(cp, df);
    warp_kernel<<<dim3(1, H_, B_), block>>>(x, df, out);
}